// round 17
// baseline (speedup 1.0000x reference)
#include <cuda_runtime.h>
#include <cstdint>

#define NEG_INF  (-1e8f)
#define M_EMPTY  (-1e30f)
#define INVLN2 1.4426950408889634f
#define LN2    0.6931471805599453f

__device__ __forceinline__ float ex2f(float x){ float r; asm("ex2.approx.ftz.f32 %0, %1;" : "=f"(r) : "f"(x)); return r; }
__device__ __forceinline__ float lg2f(float x){ float r; asm("lg2.approx.ftz.f32 %0, %1;" : "=f"(r) : "f"(x)); return r; }

__device__ __forceinline__ float lse2(float a, float b){
    float m = fmaxf(a, b);
    return m + lg2f(1.0f + ex2f(-fabsf(a - b)));
}
__device__ __forceinline__ float lse3(float a, float b, float c){
    float m = fmaxf(fmaxf(a, b), c);
    return m + lg2f(ex2f(a - m) + ex2f(b - m) + ex2f(c - m));
}
// online-softmax fold, identity (M_EMPTY, 0); branch-free
__device__ __forceinline__ void mqcomb(float& M, float& Q, float Ma, float Qa){
    float f  = ex2f(-fabsf(M - Ma));
    bool  ge = (M >= Ma);
    float q1 = fmaf(Qa, f, Q);
    float q2 = fmaf(Q,  f, Qa);
    Q = ge ? q1 : q2;
    M = fmaxf(M, Ma);
}
__device__ __forceinline__ void st_release_s32(uint32_t saddr, int v){
    asm volatile("st.release.cta.shared::cta.u32 [%0], %1;" :: "r"(saddr), "r"(v) : "memory");
}
__device__ __forceinline__ int ld_acquire_s32(uint32_t saddr){
    int v;
    asm volatile("ld.acquire.cta.shared::cta.u32 %0, [%1];" : "=r"(v) : "r"(saddr) : "memory");
    return v;
}
__device__ __forceinline__ uint32_t smem_u32(const void* p){
    return (uint32_t)__cvta_generic_to_shared(p);
}

// R12 skeleton (4-stage warp pipeline, 191us) + depth-2 prefetch:
// row r+1's coefficients are consumed (tail P-pairs) a FULL iteration after
// their loads issue, so the tail never waits on DRAM long-scoreboard.
// One CTA (4 warps) per batch; warp w owns cols [64w,64w+64), 2 cols/lane.
// Log2-domain DP, S/T factorization, MQ online-softmax scan, late-fold head
// pairs, smem carry ring with acquire/release flags between stage warps.
__global__ __launch_bounds__(128, 1)
void forward_decoder_kernel(const float* __restrict__ theta,
                            const float* __restrict__ A,
                            float* __restrict__ out){
    constexpr int N = 256;
    const int lane = threadIdx.x & 31;
    const int w    = threadIdx.x >> 5;
    const int b    = blockIdx.x;

    __shared__ float4  pay[4][8];
    __shared__ uint32_t flag[4];
    __shared__ uint32_t ack[4];
    if(threadIdx.x < 4){ flag[threadIdx.x] = 0; ack[threadIdx.x] = 0; }
    __syncthreads();   // only barrier in the kernel

    const uint32_t flag_prev = smem_u32(&flag[(w + 3) & 3]);
    const uint32_t flag_own  = smem_u32(&flag[w]);
    const uint32_t ack_own   = smem_u32(&ack[w]);
    const uint32_t ack_next  = smem_u32(&ack[(w + 1) & 3]);

    const int jc = (w << 6) + (lane << 1);
    const float* thb = theta + (size_t)b * 196608 + (size_t)jc * 3;
    const float* Ab  = A     + (size_t)b * 589824 + (size_t)jc * 9;

    auto loadrow = [&](int r, float2* p){
        const float2* tp = (const float2*)(thb + (size_t)r * 768);
        const float2* ap = (const float2*)(Ab  + (size_t)r * 2304);
        p[0]=__ldg(tp); p[1]=__ldg(tp+1); p[2]=__ldg(tp+2);
        #pragma unroll
        for(int k = 0; k < 9; k++) p[3+k] = __ldg(ap + k);
    };

    float2 bufA[12], bufB[12];
    loadrow(0, bufA);            // row 0
    loadrow(1, bufB);            // row 1

    float pv0e=NEG_INF, pv1e=NEG_INF, pv2e=NEG_INF;
    float pv0o=NEG_INF, pv1o=NEG_INF, pv2o=NEG_INF;
    float u0in=NEG_INF, u1in=NEG_INF, xin=NEG_INF;

    // prologue: head-pairs for row 0 from boundary V (NEG_INF; cell(0,0)=0)
    float bv0 = (w == 0 && lane == 0) ? 0.0f : NEG_INF;
    float Pu0e = lse2(fmaf(bufA[3].x, INVLN2, bv0),     fmaf(bufA[3].y, INVLN2, bv0));
    float Pu1e = lse2(fmaf(bufA[4].y, INVLN2, NEG_INF), fmaf(bufA[5].x, INVLN2, NEG_INF));
    float Pn0o = lse2(fmaf(bufA[7].y, INVLN2, NEG_INF), fmaf(bufA[8].x, INVLN2, NEG_INF));
    float Pn1o = lse2(fmaf(bufA[9].x, INVLN2, NEG_INF), fmaf(bufA[9].y, INVLN2, NEG_INF));
    float dlate = bv0;

    // pc = buffer holding row r (overwritten with row r+2 loads this iter);
    // pn = buffer holding row r+1 (loaded a full iteration ago; tail consumes it)
    auto body = [&](int r, float2* pc, float2* pn){
        // extract row-r scalars BEFORE overwriting pc
        float t0e=pc[0].x, t1e=pc[0].y, t2e=pc[1].x*INVLN2;
        float t0o=pc[1].y, t1o=pc[2].x, t2o=pc[2].y*INVLN2;
        float e2=pc[4].x, e5=pc[5].y, e6=pc[6].x, e7=pc[6].y, e8=pc[7].x;
        float o2=pc[8].y, o5=pc[10].x, o6=pc[10].y, o7=pc[11].x, o8=pc[11].y;

        // issue loads for row r+2 into pc (consumed next iter: full-period gap)
        if(r + 2 < N) loadrow(r + 2, pc);

        // heads: single lse2 fold of precomputed pair with the late V2 term
        float u0e  = fmaf(t0e, INVLN2, lse2(Pu0e, fmaf(e2, INVLN2, dlate)));
        float u1e  = fmaf(t1e, INVLN2, lse2(Pu1e, fmaf(e5, INVLN2, pv2e)));
        float nu0o = fmaf(t0o, INVLN2, lse2(Pn0o, fmaf(o2, INVLN2, pv2e)));
        float nu1o = fmaf(t1o, INVLN2, lse2(Pn1o, fmaf(o5, INVLN2, pv2o)));

        float num0 = __shfl_up_sync(0xffffffffu, nu0o, 1);
        float num1 = __shfl_up_sync(0xffffffffu, nu1o, 1);

        // FADD prefix-sum of a (off-chain)
        float a_e = fmaf(e8, INVLN2, t2e), a_o = fmaf(o8, INVLN2, t2o);
        float Sin = a_e + a_o;
        #pragma unroll
        for(int dlt = 1; dlt < 32; dlt <<= 1){
            float v = __shfl_up_sync(0xffffffffu, Sin, dlt);
            Sin += (lane >= dlt) ? v : 0.0f;
        }
        float Sl_o = Sin, Sl_e = Sin - a_o;

        float c_o = t2o + lse2(fmaf(o6, INVLN2, u0e),  fmaf(o7, INVLN2, u1e));
        float c_e = t2e + lse2(fmaf(e6, INVLN2, num0), fmaf(e7, INVLN2, num1));
        float Te  = (lane == 0) ? M_EMPTY : c_e - Sl_e;
        float To  = c_o - Sl_o;

        float Mi = fmaxf(Te, To);
        float Qi = 1.0f + ex2f(-fabsf(Te - To));
        #pragma unroll
        for(int dlt = 1; dlt < 32; dlt <<= 1){
            float Mn = __shfl_up_sync(0xffffffffu, Mi, dlt);
            float Qn = __shfl_up_sync(0xffffffffu, Qi, dlt);
            bool take = (lane >= dlt);
            Mn = take ? Mn : M_EMPTY;
            Qn = take ? Qn : 0.0f;
            mqcomb(Mi, Qi, Mn, Qn);
        }
        float eM = __shfl_up_sync(0xffffffffu, Mi, 1);
        float eQ = __shfl_up_sync(0xffffffffu, Qi, 1);
        float WeM = (lane == 0) ? M_EMPTY : eM;
        float WeQ = (lane == 0) ? 0.0f    : eQ;
        mqcomb(WeM, WeQ, Te, 1.0f);

        // carry from warp w-1 (row r): u0,u1,x at col 64w-1 (late wait)
        if(w > 0){
            while(ld_acquire_s32(flag_prev) < r + 1){ }
            float4 ps = pay[w-1][r & 7];
            u0in = ps.x; u1in = ps.y; xin = ps.z;
            if(lane == 0) st_release_s32(ack_own, r + 1);
        }

        // lane-0 element + incoming x folded post-scan as one (M,Q) element
        float ce0 = t2e + lse2(fmaf(e6, INVLN2, u0in), fmaf(e7, INVLN2, u1in));
        float cb  = __shfl_sync(0xffffffffu, ce0 - a_e, 0);
        float zM  = fmaxf(xin, cb);
        float zQ  = 1.0f + ex2f(-fabsf(xin - cb));

        mqcomb(WeM, WeQ, zM, zQ);
        float x_e = Sl_e + WeM + lg2f(WeQ);
        float XoM = Mi, XoQ = Qi;
        mqcomb(XoM, XoQ, zM, zQ);
        float x_o = Sl_o + XoM + lg2f(XoQ);

        // post carry to warp w+1
        if(w < 3){
            if(lane == 31){
                while(ld_acquire_s32(ack_next) < r - 7){ }
                pay[w][r & 7] = make_float4(nu0o, nu1o, x_o, 0.0f);
                st_release_s32(flag_own, r + 1);
            }
        }

        // TAIL: head-pairs for row r+1 from pn (loaded a full iter ago — no
        // long-scoreboard). Off the x-chain.
        float d0n = (lane == 0) ? u0in : num0;
        float d1n = (lane == 0) ? u1in : num1;
        Pu0e = lse2(fmaf(pn[3].x, INVLN2, d0n),  fmaf(pn[3].y, INVLN2, d1n));
        Pu1e = lse2(fmaf(pn[4].y, INVLN2, u0e),  fmaf(pn[5].x, INVLN2, u1e));
        Pn0o = lse2(fmaf(pn[7].y, INVLN2, u0e),  fmaf(pn[8].x, INVLN2, u1e));
        Pn1o = lse2(fmaf(pn[9].x, INVLN2, nu0o), fmaf(pn[9].y, INVLN2, nu1o));
        float sxo = __shfl_up_sync(0xffffffffu, x_o, 1);
        dlate = (lane == 0) ? xin : sxo;

        pv0e = u0e;  pv1e = u1e;  pv2e = x_e;
        pv0o = nu0o; pv1o = nu1o; pv2o = x_o;
    };

    for(int r = 0; r < N; r += 2){
        body(r,     bufA, bufB);   // consumes row r (bufA), loads r+2 into bufA
        body(r + 1, bufB, bufA);   // consumes row r+1 (bufB), loads r+3 into bufB
    }

    if(w == 3 && lane == 31) out[b] = LN2 * lse3(pv0o, pv1o, pv2o);
}

extern "C" void kernel_launch(void* const* d_in, const int* in_sizes, int n_in,
                              void* d_out, int out_size) {
    const float* theta = (const float*)d_in[0];
    const float* A     = (const float*)d_in[1];
    // d_in[2] = pos: fixed [(-1,-1),(-1,0),(0,-1)] -> (diag, up, left), hard-coded.
    float* out = (float*)d_out;
    int B = out_size;   // 128 batches, one CTA each
    forward_decoder_kernel<<<B, 128>>>(theta, A, out);
}